// round 1
// baseline (speedup 1.0000x reference)
#include <cuda_runtime.h>
#include <math.h>

#define OBS   128
#define PROJ  64
#define HID   256
#define LAT   24
#define BB    1024
#define TT    256
#define G3    768   // 3*HID

// Scratch: precomputed input-side gates gx = (obs@W_in + b_in)@W_ih + b_ih, [B*T, 768] fp32
__device__ float g_gx[(size_t)BB * TT * G3];

// ---------------------------------------------------------------------------
// pre_kernel: fused  x = obs@W_in + b_in ;  gx = x@W_ih + b_ih
// grid: B*T/32 CTAs, 256 threads
// ---------------------------------------------------------------------------
#define PRE_ROWS 32
__global__ __launch_bounds__(256) void pre_kernel(
    const float* __restrict__ obs, const float* __restrict__ W_in,
    const float* __restrict__ b_in, const float* __restrict__ W_ih,
    const float* __restrict__ b_ih)
{
    __shared__ float s_obs[PRE_ROWS][OBS];   // 16 KB
    __shared__ float s_x[PRE_ROWS][PROJ];    //  8 KB

    const int tid = threadIdx.x;
    const long long row0 = (long long)blockIdx.x * PRE_ROWS;

    // load obs tile (coalesced)
    for (int i = tid; i < PRE_ROWS * OBS; i += 256) {
        int r = i >> 7, c = i & 127;
        s_obs[r][c] = obs[(row0 + r) * OBS + c];
    }
    __syncthreads();

    // stage 1: x tile. thread -> col p = tid&63, rows rb, rb+4, ..., rb+28
    {
        const int p  = tid & 63;
        const int rb = tid >> 6;       // 0..3
        float acc[8];
        #pragma unroll
        for (int i = 0; i < 8; i++) acc[i] = 0.f;
        #pragma unroll 4
        for (int k = 0; k < OBS; k++) {
            float w = W_in[k * PROJ + p];      // 32 KB, L1-resident
            #pragma unroll
            for (int i = 0; i < 8; i++) acc[i] += s_obs[rb + i * 4][k] * w;
        }
        float bi = b_in[p];
        #pragma unroll
        for (int i = 0; i < 8; i++) s_x[rb + i * 4][p] = acc[i] + bi;
    }
    __syncthreads();

    // stage 2: gx. thread j owns columns {j, j+256, j+512}; 2 tiles of 16 rows
    const int j = tid;
    const float bh0 = b_ih[j], bh1 = b_ih[j + 256], bh2 = b_ih[j + 512];
    for (int rt = 0; rt < PRE_ROWS / 16; rt++) {
        float a0[16], a1[16], a2[16];
        #pragma unroll
        for (int i = 0; i < 16; i++) { a0[i] = bh0; a1[i] = bh1; a2[i] = bh2; }
        #pragma unroll 2
        for (int p = 0; p < PROJ; p++) {
            float w0 = W_ih[p * G3 + j];
            float w1 = W_ih[p * G3 + j + 256];
            float w2 = W_ih[p * G3 + j + 512];
            #pragma unroll
            for (int i = 0; i < 16; i++) {
                float xv = s_x[rt * 16 + i][p];
                a0[i] += w0 * xv; a1[i] += w1 * xv; a2[i] += w2 * xv;
            }
        }
        #pragma unroll
        for (int i = 0; i < 16; i++) {
            size_t gr = (size_t)(row0 + rt * 16 + i) * G3;
            g_gx[gr + j]       = a0[i];
            g_gx[gr + j + 256] = a1[i];
            g_gx[gr + j + 512] = a2[i];
        }
    }
}

// ---------------------------------------------------------------------------
// rec_kernel: persistent GRU scan. 128 CTAs x 512 threads, 8 batch rows/CTA.
// Thread layout: j = tid&255 owns gate columns {j, j+256, j+512};
// half = tid>>8 owns batch rows half*4 .. half*4+3.
// Mish + output projection fused per step (W_out in SMEM).
// ---------------------------------------------------------------------------
__global__ __launch_bounds__(512) void rec_kernel(
    const int* __restrict__ is_init, const float* __restrict__ hx,
    const float* __restrict__ W_hh, const float* __restrict__ b_hh,
    const float* __restrict__ W_out, const float* __restrict__ b_out,
    float* __restrict__ out, float* __restrict__ h_final)
{
    __shared__ float s_h[8][HID];            // 8 KB
    __shared__ float s_mish[8][HID];         // 8 KB
    __shared__ unsigned char s_rst[8][TT];   // 2 KB
    __shared__ float s_Wout[HID * LAT];      // 24 KB
    __shared__ float s_bout[LAT];

    const int tid  = threadIdx.x;
    const int j    = tid & 255;
    const int half = tid >> 8;               // 0/1
    const int b0   = blockIdx.x * 8;

    // init h from hx
    #pragma unroll
    for (int r = 0; r < 4; r++)
        s_h[half * 4 + r][j] = hx[(b0 + half * 4 + r) * HID + j];

    // reset mask for all steps
    for (int i = tid; i < 8 * TT; i += 512) {
        int r = i >> 8, t = i & 255;
        s_rst[r][t] = (unsigned char)(is_init[(b0 + r) * TT + t] != 0);
    }
    for (int i = tid; i < HID * LAT; i += 512) s_Wout[i] = W_out[i];
    if (tid < LAT) s_bout[tid] = b_out[tid];

    const float bh0 = b_hh[j], bh1 = b_hh[j + 256], bh2 = b_hh[j + 512];
    __syncthreads();

    const float* Wc = W_hh + j;

    for (int t = 0; t < TT; t++) {
        // prefetch input-side gates (consumed ~20K cycles later -> latency hidden)
        float gx0[4], gx1[4], gx2[4];
        #pragma unroll
        for (int r = 0; r < 4; r++) {
            size_t row = (size_t)(b0 + half * 4 + r) * TT + t;
            const float* g = g_gx + row * G3;
            gx0[r] = g[j]; gx1[r] = g[j + 256]; gx2[r] = g[j + 512];
        }

        // episode-reset mask on own column
        float hprev[4];
        #pragma unroll
        for (int r = 0; r < 4; r++) {
            float h = s_h[half * 4 + r][j];
            h = s_rst[half * 4 + r][t] ? 0.f : h;
            hprev[r] = h;
            s_h[half * 4 + r][j] = h;
        }
        __syncthreads();   // masked h visible to all

        // gh = h @ W_hh  (accumulate from zero; biases/gx folded in at gate time)
        float a0[4] = {0, 0, 0, 0}, a1[4] = {0, 0, 0, 0}, a2[4] = {0, 0, 0, 0};
        #pragma unroll 4
        for (int k = 0; k < HID; k++) {
            float w0 = Wc[(size_t)k * G3];
            float w1 = Wc[(size_t)k * G3 + 256];
            float w2 = Wc[(size_t)k * G3 + 512];
            #pragma unroll
            for (int r = 0; r < 4; r++) {
                float hk = s_h[half * 4 + r][k];   // LDS broadcast
                a0[r] += w0 * hk; a1[r] += w1 * hk; a2[r] += w2 * hk;
            }
        }

        // gates + mish in registers
        float hnew[4], mi[4];
        #pragma unroll
        for (int r = 0; r < 4; r++) {
            float ghr = a0[r] + bh0;
            float ghz = a1[r] + bh1;
            float ghn = a2[r] + bh2;
            float rg = 1.f / (1.f + expf(-(gx0[r] + ghr)));
            float zg = 1.f / (1.f + expf(-(gx1[r] + ghz)));
            float ng = tanhf(gx2[r] + rg * ghn);
            float h  = (1.f - zg) * ng + zg * hprev[r];
            hnew[r] = h;
            mi[r]   = h * tanhf(log1pf(expf(h)));   // mish; |h|<=1 so no overflow
        }
        __syncthreads();   // all gh reads of s_h complete
        #pragma unroll
        for (int r = 0; r < 4; r++) {
            s_h[half * 4 + r][j]    = hnew[r];
            s_mish[half * 4 + r][j] = mi[r];
        }
        __syncthreads();   // h_new + mish visible

        // fused output projection: 192 threads, out[b, t, :] = mish @ W_out + b_out
        if (tid < 8 * LAT) {
            int r = tid / LAT, l = tid % LAT;
            float acc = s_bout[l];
            #pragma unroll 8
            for (int k2 = 0; k2 < HID; k2++)
                acc += s_mish[r][k2] * s_Wout[k2 * LAT + l];
            out[((size_t)(b0 + r) * TT + t) * LAT + l] = acc;
        }
        // next iter's mask-write to s_h races only with s_mish reads above: disjoint.
    }

    // h_final = h after last step (own writes; no sync needed)
    #pragma unroll
    for (int r = 0; r < 4; r++)
        h_final[(b0 + half * 4 + r) * HID + j] = s_h[half * 4 + r][j];
}

// ---------------------------------------------------------------------------
extern "C" void kernel_launch(void* const* d_in, const int* in_sizes, int n_in,
                              void* d_out, int out_size) {
    const float* obs     = (const float*)d_in[0];
    const int*   is_init = (const int*)  d_in[1];
    const float* hx      = (const float*)d_in[2];
    const float* W_in    = (const float*)d_in[3];
    const float* b_in    = (const float*)d_in[4];
    const float* W_ih    = (const float*)d_in[5];
    const float* b_ih    = (const float*)d_in[6];
    const float* W_hh    = (const float*)d_in[7];
    const float* b_hh    = (const float*)d_in[8];
    const float* W_out   = (const float*)d_in[9];
    const float* b_out   = (const float*)d_in[10];

    float* out     = (float*)d_out;                       // [B,T,LAT]
    float* h_final = out + (size_t)BB * TT * LAT;         // [B,HID]

    pre_kernel<<<(BB * TT) / PRE_ROWS, 256>>>(obs, W_in, b_in, W_ih, b_ih);
    rec_kernel<<<BB / 8, 512>>>(is_init, hx, W_hh, b_hh, W_out, b_out, out, h_final);
}

// round 2
// speedup vs baseline: 2.0659x; 2.0659x over previous
#include <cuda_runtime.h>
#include <math.h>
#include <stdint.h>

#define OBS   128
#define PROJ  64
#define HID   256
#define LAT   24
#define BB    1024
#define TT    256
#define G3    768

// ---- device scratch --------------------------------------------------------
__device__ float  g_gx [(size_t)BB * TT * G3];   // input-side gates [B*T,768]
__device__ float  g_seq[(size_t)BB * TT * HID];  // h_new per step   [B*T,256]
__device__ float4 g_Wt4[(HID / 4) * G3];         // W_hh repacked [k4][col] float4

// ---- helpers ---------------------------------------------------------------
__device__ __forceinline__ void fma2(float2& d, float2 a, float2 b) {
    unsigned long long& dd = reinterpret_cast<unsigned long long&>(d);
    asm("fma.rn.f32x2 %0, %1, %2, %0;"
        : "+l"(dd)
        : "l"(reinterpret_cast<const unsigned long long&>(a)),
          "l"(reinterpret_cast<const unsigned long long&>(b)));
}
__device__ __forceinline__ float fsig(float x) {
    return __fdividef(1.f, 1.f + __expf(-x));
}
__device__ __forceinline__ float ftanh(float x) {
    return 2.f * fsig(2.f * x) - 1.f;
}

// ---- W_hh repack: g_Wt4[k4*768+col] = {W[4k4][col],...,W[4k4+3][col]} ------
__global__ void tr_kernel(const float* __restrict__ W) {
    int idx = blockIdx.x * 256 + threadIdx.x;
    if (idx >= (HID / 4) * G3) return;
    int k4 = idx / G3, col = idx - k4 * G3;
    float4 v;
    v.x = W[(size_t)(4 * k4 + 0) * G3 + col];
    v.y = W[(size_t)(4 * k4 + 1) * G3 + col];
    v.z = W[(size_t)(4 * k4 + 2) * G3 + col];
    v.w = W[(size_t)(4 * k4 + 3) * G3 + col];
    g_Wt4[idx] = v;
}

// ---- pre: gx = (obs@W_in + b_in)@W_ih + b_ih, FFMA2-packed over row pairs --
__global__ __launch_bounds__(256) void pre_kernel(
    const float* __restrict__ obs, const float* __restrict__ W_in,
    const float* __restrict__ b_in, const float* __restrict__ W_ih,
    const float* __restrict__ b_ih)
{
    __shared__ float s_obsT[OBS][34];   // [k][row], pad 34 (even -> f2 aligned)
    __shared__ float s_x2[PROJ][34];    // [p][row]

    const int tid = threadIdx.x;
    const size_t row0 = (size_t)blockIdx.x * 32;

    for (int i = tid; i < 32 * OBS; i += 256) {
        int r = i >> 7, k = i & 127;
        s_obsT[k][r] = obs[(row0 + r) * OBS + k];
    }
    __syncthreads();

    // stage 1: x = obs@W_in + b_in. thread: col p, rows 8rh..8rh+7 (4 pairs)
    {
        const int p = tid & 63, rh = tid >> 6;
        const float bi = b_in[p];
        float2 acc[4];
        #pragma unroll
        for (int pr = 0; pr < 4; pr++) acc[pr] = make_float2(bi, bi);
        #pragma unroll 4
        for (int k = 0; k < OBS; k++) {
            float w = W_in[k * PROJ + p];
            float2 w2 = make_float2(w, w);
            #pragma unroll
            for (int pr = 0; pr < 4; pr++)
                fma2(acc[pr], w2, *(const float2*)&s_obsT[k][8 * rh + 2 * pr]);
        }
        #pragma unroll
        for (int pr = 0; pr < 4; pr++) {
            s_x2[p][8 * rh + 2 * pr]     = acc[pr].x;
            s_x2[p][8 * rh + 2 * pr + 1] = acc[pr].y;
        }
    }
    __syncthreads();

    // stage 2: gx = x@W_ih + b_ih. thread j owns cols {j, j+256, j+512}
    const int j = tid;
    const float bh0 = b_ih[j], bh1 = b_ih[j + 256], bh2 = b_ih[j + 512];
    for (int rt = 0; rt < 2; rt++) {           // two 16-row tiles (8 pairs)
        float2 a0[8], a1[8], a2[8];
        #pragma unroll
        for (int pr = 0; pr < 8; pr++) {
            a0[pr] = make_float2(bh0, bh0);
            a1[pr] = make_float2(bh1, bh1);
            a2[pr] = make_float2(bh2, bh2);
        }
        #pragma unroll 2
        for (int p = 0; p < PROJ; p++) {
            float w0 = W_ih[p * G3 + j];
            float w1 = W_ih[p * G3 + j + 256];
            float w2 = W_ih[p * G3 + j + 512];
            float2 w02 = make_float2(w0, w0);
            float2 w12 = make_float2(w1, w1);
            float2 w22 = make_float2(w2, w2);
            #pragma unroll
            for (int pr = 0; pr < 8; pr++) {
                float2 xv = *(const float2*)&s_x2[p][16 * rt + 2 * pr];
                fma2(a0[pr], w02, xv);
                fma2(a1[pr], w12, xv);
                fma2(a2[pr], w22, xv);
            }
        }
        #pragma unroll
        for (int pr = 0; pr < 8; pr++) {
            size_t r = row0 + rt * 16 + 2 * pr;
            g_gx[r * G3 + j]             = a0[pr].x;
            g_gx[(r + 1) * G3 + j]       = a0[pr].y;
            g_gx[r * G3 + j + 256]       = a1[pr].x;
            g_gx[(r + 1) * G3 + j + 256] = a1[pr].y;
            g_gx[r * G3 + j + 512]       = a2[pr].x;
            g_gx[(r + 1) * G3 + j + 512] = a2[pr].y;
        }
    }
}

// ---- rec: cluster-2 persistent GRU scan ------------------------------------
// 64 clusters x 2 CTAs. Cluster c: batch rows 16c..16c+15.
// CTA rank q: hidden units q*128..q*128+127 (cols gu, 256+gu, 512+gu).
// Thread: uu = tid&127 (unit), rg = tid>>7 (row-half: rows 8rg..8rg+7).
// h kept in SMEM pair-packed: s_hp[buf][k][pair] = (h[2p][k], h[2p+1][k]).
// Each step: GEMV (FFMA2) -> gates -> store h to g_seq -> write masked h
// (local + peer via DSMEM) -> barrier.cluster.
__global__ __launch_bounds__(256) __cluster_dims__(2, 1, 1)
void rec_kernel(const int* __restrict__ is_init, const float* __restrict__ hx,
                const float* __restrict__ b_hh, float* __restrict__ h_final)
{
    __shared__ float2 s_hp[2][HID][8];          // 32 KB
    __shared__ unsigned char s_rst[16][TT];     //  4 KB

    const int tid = threadIdx.x;
    const int q   = blockIdx.x & 1;
    const int b0  = (blockIdx.x >> 1) * 16;
    const int uu  = tid & 127;
    const int rg  = tid >> 7;
    const int gu  = q * 128 + uu;
    const int p0  = rg * 4;
    const int r0  = rg * 8;

    for (int i = tid; i < 16 * TT; i += 256) {
        int r = i >> 8, t = i & 255;
        s_rst[r][t] = (unsigned char)(is_init[(b0 + r) * TT + t] != 0);
    }
    // init buffer 0 with t=0-masked hx (all 256 units, own CTA only)
    for (int i = tid; i < HID * 8; i += 256) {
        int k = i >> 3, p = i & 7;
        float h0 = (is_init[(b0 + 2 * p) * TT] != 0)     ? 0.f : hx[(b0 + 2 * p) * HID + k];
        float h1 = (is_init[(b0 + 2 * p + 1) * TT] != 0) ? 0.f : hx[(b0 + 2 * p + 1) * HID + k];
        s_hp[0][k][p] = make_float2(h0, h1);
    }
    __syncthreads();

    const float bhr = b_hh[gu], bhz = b_hh[256 + gu], bhn = b_hh[512 + gu];

    uint32_t my_base;
    asm("{ .reg .u64 t0; cvta.to.shared.u64 t0, %1; cvt.u32.u64 %0, t0; }"
        : "=r"(my_base) : "l"(&s_hp[0][0][0]));
    uint32_t peer_base;
    asm("mapa.shared::cluster.u32 %0, %1, %2;"
        : "=r"(peer_base) : "r"(my_base), "r"(q ^ 1));

    for (int t = 0; t < TT; t++) {
        const int rb = t & 1, wb = rb ^ 1;

        // prefetch input-side gates (consumed after GEMV -> latency hidden)
        float gxr[8], gxz[8], gxn[8];
        #pragma unroll
        for (int r = 0; r < 8; r++) {
            const float* g = g_gx + ((size_t)(b0 + r0 + r) * TT + t) * G3;
            gxr[r] = g[gu]; gxz[r] = g[256 + gu]; gxn[r] = g[512 + gu];
        }
        float hprev[8];
        #pragma unroll
        for (int p = 0; p < 4; p++) {
            float2 v = s_hp[rb][gu][p0 + p];
            hprev[2 * p] = v.x; hprev[2 * p + 1] = v.y;
        }

        // GEMV: gh[col] = sum_k h[k] * W_hh[k][col], FFMA2 over row pairs
        float2 ar[4], az[4], an[4];
        #pragma unroll
        for (int p = 0; p < 4; p++) {
            ar[p] = make_float2(0.f, 0.f);
            az[p] = make_float2(0.f, 0.f);
            an[p] = make_float2(0.f, 0.f);
        }
        #pragma unroll 4
        for (int k4 = 0; k4 < HID / 4; k4++) {
            float4 wr = g_Wt4[k4 * G3 + gu];
            float4 wz = g_Wt4[k4 * G3 + 256 + gu];
            float4 wn = g_Wt4[k4 * G3 + 512 + gu];
            float wra[4] = {wr.x, wr.y, wr.z, wr.w};
            float wza[4] = {wz.x, wz.y, wz.z, wz.w};
            float wna[4] = {wn.x, wn.y, wn.z, wn.w};
            #pragma unroll
            for (int kk = 0; kk < 4; kk++) {
                int k = 4 * k4 + kk;
                float4 hA = *(const float4*)&s_hp[rb][k][p0];
                float4 hB = *(const float4*)&s_hp[rb][k][p0 + 2];
                float2 h0 = make_float2(hA.x, hA.y);
                float2 h1 = make_float2(hA.z, hA.w);
                float2 h2 = make_float2(hB.x, hB.y);
                float2 h3 = make_float2(hB.z, hB.w);
                float2 w2;
                w2 = make_float2(wra[kk], wra[kk]);
                fma2(ar[0], w2, h0); fma2(ar[1], w2, h1);
                fma2(ar[2], w2, h2); fma2(ar[3], w2, h3);
                w2 = make_float2(wza[kk], wza[kk]);
                fma2(az[0], w2, h0); fma2(az[1], w2, h1);
                fma2(az[2], w2, h2); fma2(az[3], w2, h3);
                w2 = make_float2(wna[kk], wna[kk]);
                fma2(an[0], w2, h0); fma2(an[1], w2, h1);
                fma2(an[2], w2, h2); fma2(an[3], w2, h3);
            }
        }

        // gates
        float hnew[8];
        #pragma unroll
        for (int p = 0; p < 4; p++) {
            float gr[2] = {ar[p].x, ar[p].y};
            float gz[2] = {az[p].x, az[p].y};
            float gn[2] = {an[p].x, an[p].y};
            #pragma unroll
            for (int e = 0; e < 2; e++) {
                int r = 2 * p + e;
                float rr = fsig(gxr[r] + gr[e] + bhr);
                float zz = fsig(gxz[r] + gz[e] + bhz);
                float nn = ftanh(gxn[r] + rr * (gn[e] + bhn));
                hnew[r] = nn + zz * (hprev[r] - nn);
            }
        }

        // store h_new (unmasked) for epilogue
        #pragma unroll
        for (int r = 0; r < 8; r++)
            g_seq[((size_t)(b0 + r0 + r) * TT + t) * HID + gu] = hnew[r];

        if (t == TT - 1) {
            #pragma unroll
            for (int r = 0; r < 8; r++)
                h_final[(b0 + r0 + r) * HID + gu] = hnew[r];
            break;
        }

        // write (t+1)-masked h pairs to both CTAs' write buffer
        #pragma unroll
        for (int p = 0; p < 4; p++) {
            float2 v;
            v.x = s_rst[r0 + 2 * p][t + 1]     ? 0.f : hnew[2 * p];
            v.y = s_rst[r0 + 2 * p + 1][t + 1] ? 0.f : hnew[2 * p + 1];
            s_hp[wb][gu][p0 + p] = v;
            uint32_t off = (uint32_t)(((wb * HID + gu) * 8 + p0 + p) * sizeof(float2));
            asm volatile("st.shared::cluster.b64 [%0], %1;"
                         :: "r"(peer_base + off),
                            "l"(*(const unsigned long long*)&v) : "memory");
        }

        asm volatile("barrier.cluster.arrive.aligned;" ::: "memory");
        asm volatile("barrier.cluster.wait.aligned;" ::: "memory");
    }
}

// ---- post: out = mish(seq) @ W_out + b_out ---------------------------------
__global__ __launch_bounds__(384) void post_kernel(
    const float* __restrict__ W_out, const float* __restrict__ b_out,
    float* __restrict__ out)
{
    __shared__ float s_m[16][HID];     // 16 KB
    __shared__ float s_w[HID * LAT];   // 24 KB
    __shared__ float s_b[LAT];

    const int tid = threadIdx.x;
    const size_t row0 = (size_t)blockIdx.x * 16;

    for (int i = tid; i < HID * LAT; i += 384) s_w[i] = W_out[i];
    if (tid < LAT) s_b[tid] = b_out[tid];
    for (int i = tid; i < 16 * HID; i += 384) {
        int r = i >> 8, k = i & 255;
        float h = g_seq[(row0 + r) * HID + k];
        float sp = __logf(1.f + __expf(h));
        s_m[r][k] = h * ftanh(sp);
    }
    __syncthreads();

    if (tid < 16 * LAT) {
        int r = tid / LAT, l = tid - r * LAT;
        float acc = s_b[l];
        #pragma unroll 8
        for (int k = 0; k < HID; k++)
            acc = fmaf(s_m[r][k], s_w[k * LAT + l], acc);
        out[(row0 + r) * LAT + l] = acc;
    }
}

// ---------------------------------------------------------------------------
extern "C" void kernel_launch(void* const* d_in, const int* in_sizes, int n_in,
                              void* d_out, int out_size) {
    const float* obs     = (const float*)d_in[0];
    const int*   is_init = (const int*)  d_in[1];
    const float* hx      = (const float*)d_in[2];
    const float* W_in    = (const float*)d_in[3];
    const float* b_in    = (const float*)d_in[4];
    const float* W_ih    = (const float*)d_in[5];
    const float* b_ih    = (const float*)d_in[6];
    const float* W_hh    = (const float*)d_in[7];
    const float* b_hh    = (const float*)d_in[8];
    const float* W_out   = (const float*)d_in[9];
    const float* b_out   = (const float*)d_in[10];

    float* out     = (float*)d_out;                 // [B,T,LAT]
    float* h_final = out + (size_t)BB * TT * LAT;   // [B,HID]

    tr_kernel<<<((HID / 4) * G3 + 255) / 256, 256>>>(W_hh);
    pre_kernel<<<(BB * TT) / 32, 256>>>(obs, W_in, b_in, W_ih, b_ih);
    rec_kernel<<<BB / 8, 256>>>(is_init, hx, b_hh, h_final);
    post_kernel<<<(BB * TT) / 16, 384>>>(W_out, b_out, out);
}

// round 3
// speedup vs baseline: 2.3706x; 1.1475x over previous
#include <cuda_runtime.h>
#include <math.h>
#include <stdint.h>

#define OBS   128
#define PROJ  64
#define HID   256
#define LAT   24
#define BB    1024
#define TT    256
#define G3    768

// ---- device scratch --------------------------------------------------------
__device__ float  g_gx [(size_t)BB * TT * G3];   // input-side gates [B*T,768]
__device__ float  g_seq[(size_t)BB * TT * HID];  // h_new per step   [B*T,256]
__device__ float4 g_Wt4[(HID / 4) * G3];         // W_hh repacked [k4][col] float4

// ---- helpers ---------------------------------------------------------------
__device__ __forceinline__ void fma2(float2& d, float2 a, float2 b) {
    unsigned long long& dd = reinterpret_cast<unsigned long long&>(d);
    asm("fma.rn.f32x2 %0, %1, %2, %0;"
        : "+l"(dd)
        : "l"(reinterpret_cast<const unsigned long long&>(a)),
          "l"(reinterpret_cast<const unsigned long long&>(b)));
}
__device__ __forceinline__ float tanha(float x) {
    float y; asm("tanh.approx.f32 %0, %1;" : "=f"(y) : "f"(x)); return y;
}
__device__ __forceinline__ float siga(float x) {       // sigmoid via MUFU.TANH
    return fmaf(0.5f, tanha(0.5f * x), 0.5f);
}

// ---- W_hh repack: g_Wt4[k4*768+col] = {W[4k4][col],...,W[4k4+3][col]} ------
__global__ void tr_kernel(const float* __restrict__ W) {
    int idx = blockIdx.x * 256 + threadIdx.x;
    if (idx >= (HID / 4) * G3) return;
    int k4 = idx / G3, col = idx - k4 * G3;
    float4 v;
    v.x = W[(size_t)(4 * k4 + 0) * G3 + col];
    v.y = W[(size_t)(4 * k4 + 1) * G3 + col];
    v.z = W[(size_t)(4 * k4 + 2) * G3 + col];
    v.w = W[(size_t)(4 * k4 + 3) * G3 + col];
    g_Wt4[idx] = v;
}

// ---- pre: gx = (obs@W_in + b_in)@W_ih + b_ih, FFMA2-packed over row pairs --
__global__ __launch_bounds__(256) void pre_kernel(
    const float* __restrict__ obs, const float* __restrict__ W_in,
    const float* __restrict__ b_in, const float* __restrict__ W_ih,
    const float* __restrict__ b_ih)
{
    __shared__ float s_obsT[OBS][34];
    __shared__ float s_x2[PROJ][34];

    const int tid = threadIdx.x;
    const size_t row0 = (size_t)blockIdx.x * 32;

    for (int i = tid; i < 32 * OBS; i += 256) {
        int r = i >> 7, k = i & 127;
        s_obsT[k][r] = obs[(row0 + r) * OBS + k];
    }
    __syncthreads();

    {
        const int p = tid & 63, rh = tid >> 6;
        const float bi = b_in[p];
        float2 acc[4];
        #pragma unroll
        for (int pr = 0; pr < 4; pr++) acc[pr] = make_float2(bi, bi);
        #pragma unroll 4
        for (int k = 0; k < OBS; k++) {
            float w = W_in[k * PROJ + p];
            float2 w2 = make_float2(w, w);
            #pragma unroll
            for (int pr = 0; pr < 4; pr++)
                fma2(acc[pr], w2, *(const float2*)&s_obsT[k][8 * rh + 2 * pr]);
        }
        #pragma unroll
        for (int pr = 0; pr < 4; pr++) {
            s_x2[p][8 * rh + 2 * pr]     = acc[pr].x;
            s_x2[p][8 * rh + 2 * pr + 1] = acc[pr].y;
        }
    }
    __syncthreads();

    const int j = tid;
    const float bh0 = b_ih[j], bh1 = b_ih[j + 256], bh2 = b_ih[j + 512];
    for (int rt = 0; rt < 2; rt++) {
        float2 a0[8], a1[8], a2[8];
        #pragma unroll
        for (int pr = 0; pr < 8; pr++) {
            a0[pr] = make_float2(bh0, bh0);
            a1[pr] = make_float2(bh1, bh1);
            a2[pr] = make_float2(bh2, bh2);
        }
        #pragma unroll 2
        for (int p = 0; p < PROJ; p++) {
            float w0 = W_ih[p * G3 + j];
            float w1 = W_ih[p * G3 + j + 256];
            float w2 = W_ih[p * G3 + j + 512];
            float2 w02 = make_float2(w0, w0);
            float2 w12 = make_float2(w1, w1);
            float2 w22 = make_float2(w2, w2);
            #pragma unroll
            for (int pr = 0; pr < 8; pr++) {
                float2 xv = *(const float2*)&s_x2[p][16 * rt + 2 * pr];
                fma2(a0[pr], w02, xv);
                fma2(a1[pr], w12, xv);
                fma2(a2[pr], w22, xv);
            }
        }
        #pragma unroll
        for (int pr = 0; pr < 8; pr++) {
            size_t r = row0 + rt * 16 + 2 * pr;
            g_gx[r * G3 + j]             = a0[pr].x;
            g_gx[(r + 1) * G3 + j]       = a0[pr].y;
            g_gx[r * G3 + j + 256]       = a1[pr].x;
            g_gx[(r + 1) * G3 + j + 256] = a1[pr].y;
            g_gx[r * G3 + j + 512]       = a2[pr].x;
            g_gx[(r + 1) * G3 + j + 512] = a2[pr].y;
        }
    }
}

// ---- rec: cluster-2 persistent GRU scan, software-pipelined weights --------
#define LDW(dst, sbb)                                           \
    {                                                           \
        _Pragma("unroll")                                       \
        for (int u = 0; u < 4; u++) {                           \
            size_t kb = (size_t)(4 * (sbb) + u) * G3;           \
            dst[3 * u + 0] = g_Wt4[kb + gu];                    \
            dst[3 * u + 1] = g_Wt4[kb + 256 + gu];              \
            dst[3 * u + 2] = g_Wt4[kb + 512 + gu];              \
        }                                                       \
    }

#define COMPUTE_SB(buf, sbb)                                                  \
    {                                                                         \
        _Pragma("unroll")                                                     \
        for (int u = 0; u < 4; u++) {                                         \
            float4 wr = buf[3 * u], wz = buf[3 * u + 1], wn = buf[3 * u + 2]; \
            float wra[4] = {wr.x, wr.y, wr.z, wr.w};                          \
            float wza[4] = {wz.x, wz.y, wz.z, wz.w};                          \
            float wna[4] = {wn.x, wn.y, wn.z, wn.w};                          \
            _Pragma("unroll")                                                 \
            for (int kk = 0; kk < 4; kk++) {                                  \
                int k = 16 * (sbb) + 4 * u + kk;                              \
                float4 hA = *(const float4*)&s_hp[rb][k][p0];                 \
                float4 hB = *(const float4*)&s_hp[rb][k][p0 + 2];             \
                float2 h0 = make_float2(hA.x, hA.y);                          \
                float2 h1 = make_float2(hA.z, hA.w);                          \
                float2 h2 = make_float2(hB.x, hB.y);                          \
                float2 h3 = make_float2(hB.z, hB.w);                          \
                float2 w2;                                                    \
                w2 = make_float2(wra[kk], wra[kk]);                           \
                fma2(ar[0], w2, h0); fma2(ar[1], w2, h1);                     \
                fma2(ar[2], w2, h2); fma2(ar[3], w2, h3);                     \
                w2 = make_float2(wza[kk], wza[kk]);                           \
                fma2(az[0], w2, h0); fma2(az[1], w2, h1);                     \
                fma2(az[2], w2, h2); fma2(az[3], w2, h3);                     \
                w2 = make_float2(wna[kk], wna[kk]);                           \
                fma2(an[0], w2, h0); fma2(an[1], w2, h1);                     \
                fma2(an[2], w2, h2); fma2(an[3], w2, h3);                     \
            }                                                                 \
        }                                                                     \
    }

__global__ __launch_bounds__(256) __cluster_dims__(2, 1, 1)
void rec_kernel(const int* __restrict__ is_init, const float* __restrict__ hx,
                const float* __restrict__ b_hh, float* __restrict__ h_final)
{
    __shared__ float2 s_hp[2][HID][8];          // 32 KB
    __shared__ unsigned char s_rst[16][TT];     //  4 KB

    const int tid = threadIdx.x;
    const int q   = blockIdx.x & 1;
    const int b0  = (blockIdx.x >> 1) * 16;
    const int uu  = tid & 127;
    const int rg  = tid >> 7;
    const int gu  = q * 128 + uu;
    const int p0  = rg * 4;
    const int r0  = rg * 8;

    for (int i = tid; i < 16 * TT; i += 256) {
        int r = i >> 8, t = i & 255;
        s_rst[r][t] = (unsigned char)(is_init[(b0 + r) * TT + t] != 0);
    }
    for (int i = tid; i < HID * 8; i += 256) {
        int k = i >> 3, p = i & 7;
        float h0 = (is_init[(b0 + 2 * p) * TT] != 0)     ? 0.f : hx[(b0 + 2 * p) * HID + k];
        float h1 = (is_init[(b0 + 2 * p + 1) * TT] != 0) ? 0.f : hx[(b0 + 2 * p + 1) * HID + k];
        s_hp[0][k][p] = make_float2(h0, h1);
    }
    __syncthreads();

    const float bhr = b_hh[gu], bhz = b_hh[256 + gu], bhn = b_hh[512 + gu];

    uint32_t my_base;
    asm("{ .reg .u64 t0; cvta.to.shared.u64 t0, %1; cvt.u32.u64 %0, t0; }"
        : "=r"(my_base) : "l"(&s_hp[0][0][0]));
    uint32_t peer_base;
    asm("mapa.shared::cluster.u32 %0, %1, %2;"
        : "=r"(peer_base) : "r"(my_base), "r"(q ^ 1));

    for (int t = 0; t < TT; t++) {
        const int rb = t & 1, wb = rb ^ 1;

        // prefetch input-side gates (consumed after GEMV)
        float gxr[8], gxz[8], gxn[8];
        #pragma unroll
        for (int r = 0; r < 8; r++) {
            const float* g = g_gx + ((size_t)(b0 + r0 + r) * TT + t) * G3;
            gxr[r] = g[gu]; gxz[r] = g[256 + gu]; gxn[r] = g[512 + gu];
        }
        float hprev[8];
        #pragma unroll
        for (int p = 0; p < 4; p++) {
            float2 v = s_hp[rb][gu][p0 + p];
            hprev[2 * p] = v.x; hprev[2 * p + 1] = v.y;
        }

        // GEMV with 2-superblock-deep weight pipeline (16 k per superblock)
        float2 ar[4], az[4], an[4];
        #pragma unroll
        for (int p = 0; p < 4; p++) {
            ar[p] = make_float2(0.f, 0.f);
            az[p] = make_float2(0.f, 0.f);
            an[p] = make_float2(0.f, 0.f);
        }
        float4 wb0[12], wb1[12];
        LDW(wb0, 0);
        LDW(wb1, 1);
        #pragma unroll 1
        for (int sb = 0; sb < 14; sb += 2) {
            COMPUTE_SB(wb0, sb);
            LDW(wb0, sb + 2);
            COMPUTE_SB(wb1, sb + 1);
            LDW(wb1, sb + 3);
        }
        COMPUTE_SB(wb0, 14);
        COMPUTE_SB(wb1, 15);

        // gates (MUFU.TANH)
        float hnew[8];
        #pragma unroll
        for (int p = 0; p < 4; p++) {
            float gr[2] = {ar[p].x, ar[p].y};
            float gz[2] = {az[p].x, az[p].y};
            float gn[2] = {an[p].x, an[p].y};
            #pragma unroll
            for (int e = 0; e < 2; e++) {
                int r = 2 * p + e;
                float rr = siga(gxr[r] + gr[e] + bhr);
                float zz = siga(gxz[r] + gz[e] + bhz);
                float nn = tanha(gxn[r] + rr * (gn[e] + bhn));
                hnew[r] = nn + zz * (hprev[r] - nn);
            }
        }

        if (t == TT - 1) {
            #pragma unroll
            for (int r = 0; r < 8; r++) {
                g_seq[((size_t)(b0 + r0 + r) * TT + t) * HID + gu] = hnew[r];
                h_final[(b0 + r0 + r) * HID + gu] = hnew[r];
            }
            break;
        }

        // write (t+1)-masked h pairs locally + to peer, then barrier with
        // the g_seq stores overlapped between arrive and wait.
        #pragma unroll
        for (int p = 0; p < 4; p++) {
            float2 v;
            v.x = s_rst[r0 + 2 * p][t + 1]     ? 0.f : hnew[2 * p];
            v.y = s_rst[r0 + 2 * p + 1][t + 1] ? 0.f : hnew[2 * p + 1];
            s_hp[wb][gu][p0 + p] = v;
            uint32_t off = (uint32_t)(((wb * HID + gu) * 8 + p0 + p) * sizeof(float2));
            asm volatile("st.shared::cluster.b64 [%0], %1;"
                         :: "r"(peer_base + off),
                            "l"(*(const unsigned long long*)&v) : "memory");
        }
        asm volatile("barrier.cluster.arrive.aligned;" ::: "memory");
        #pragma unroll
        for (int r = 0; r < 8; r++)
            g_seq[((size_t)(b0 + r0 + r) * TT + t) * HID + gu] = hnew[r];
        asm volatile("barrier.cluster.wait.aligned;" ::: "memory");
    }
}

// ---- post: out = mish(seq) @ W_out + b_out (FFMA2 GEMV) --------------------
// 8192 CTAs x 256 threads, 32 rows/CTA.
// Stage A: lane=row loads g_seq (each thread consumes one full 128B line),
//          computes mish, stores transposed s_m2[k][row] (conflict-free).
// Stage B: 192 threads: thread = (outcol l, pair-group pg of 2 row-pairs).
__global__ __launch_bounds__(256) void post_kernel(
    const float* __restrict__ W_out, const float* __restrict__ b_out,
    float* __restrict__ out)
{
    __shared__ float s_m2[HID][32];   // 32 KB, [k][row]

    const int tid = threadIdx.x;
    const size_t row0 = (size_t)blockIdx.x * 32;

    // stage A
    {
        const int row = tid & 31;
        const int kc  = (tid >> 5) * 32;          // 8 chunks of 32 k
        const float* src = g_seq + (row0 + row) * HID + kc;
        #pragma unroll
        for (int c = 0; c < 8; c++) {
            float4 v = *(const float4*)(src + 4 * c);
            float hv[4] = {v.x, v.y, v.z, v.w};
            #pragma unroll
            for (int e = 0; e < 4; e++) {
                float h = hv[e];
                float sp = __logf(1.f + __expf(h));
                s_m2[kc + 4 * c + e][row] = h * tanha(sp);
            }
        }
    }
    __syncthreads();

    // stage B
    if (tid < 192) {
        const int pg = tid / 24;          // 0..7 -> rows 4pg..4pg+3
        const int l  = tid - pg * 24;     // 0..23
        float2 a0 = make_float2(0.f, 0.f), a1 = make_float2(0.f, 0.f);
        #pragma unroll 4
        for (int k = 0; k < HID; k++) {
            float4 m4 = *(const float4*)&s_m2[k][4 * pg];
            float w = __ldg(W_out + k * LAT + l);
            float2 w2 = make_float2(w, w);
            fma2(a0, w2, make_float2(m4.x, m4.y));
            fma2(a1, w2, make_float2(m4.z, m4.w));
        }
        const float bl = b_out[l];
        out[(row0 + 4 * pg + 0) * LAT + l] = a0.x + bl;
        out[(row0 + 4 * pg + 1) * LAT + l] = a0.y + bl;
        out[(row0 + 4 * pg + 2) * LAT + l] = a1.x + bl;
        out[(row0 + 4 * pg + 3) * LAT + l] = a1.y + bl;
    }
}

// ---------------------------------------------------------------------------
extern "C" void kernel_launch(void* const* d_in, const int* in_sizes, int n_in,
                              void* d_out, int out_size) {
    const float* obs     = (const float*)d_in[0];
    const int*   is_init = (const int*)  d_in[1];
    const float* hx      = (const float*)d_in[2];
    const float* W_in    = (const float*)d_in[3];
    const float* b_in    = (const float*)d_in[4];
    const float* W_ih    = (const float*)d_in[5];
    const float* b_ih    = (const float*)d_in[6];
    const float* W_hh    = (const float*)d_in[7];
    const float* b_hh    = (const float*)d_in[8];
    const float* W_out   = (const float*)d_in[9];
    const float* b_out   = (const float*)d_in[10];

    float* out     = (float*)d_out;                 // [B,T,LAT]
    float* h_final = out + (size_t)BB * TT * LAT;   // [B,HID]

    tr_kernel<<<((HID / 4) * G3 + 255) / 256, 256>>>(W_hh);
    pre_kernel<<<(BB * TT) / 32, 256>>>(obs, W_in, b_in, W_ih, b_ih);
    rec_kernel<<<BB / 8, 256>>>(is_init, hx, b_hh, h_final);
    post_kernel<<<(BB * TT) / 32, 256>>>(W_out, b_out, out);
}